// round 4
// baseline (speedup 1.0000x reference)
#include <cuda_runtime.h>

// CCC loss: B=512 rows, T=65536 cols, fp32.
// One CTA per row (512 x 512), unroll 4 (lower MLP_p1 -> less L1tex-queue
// spread per B300 model), streaming loads (__ldcs, read-once data),
// fused last-block finalize (threadfence-reduction pattern).

#define B 512
#define T 65536
#define THREADS 512
#define EPS 1e-8f

__device__ float g_partials[B * 5];
__device__ unsigned int g_count;  // zero-init; reset by last block

__device__ __forceinline__ float warp_sum(float v) {
    #pragma unroll
    for (int o = 16; o > 0; o >>= 1)
        v += __shfl_down_sync(0xFFFFFFFFu, v, o);
    return v;
}

__global__ __launch_bounds__(THREADS)
void ccc_fused(const float* __restrict__ preds,
               const float* __restrict__ labels,
               float* __restrict__ out) {
    const int row  = blockIdx.x;
    const int tid  = threadIdx.x;
    const int lane = tid & 31;
    const int wid  = tid >> 5;

    const float4* px = reinterpret_cast<const float4*>(preds  + (size_t)row * T);
    const float4* py = reinterpret_cast<const float4*>(labels + (size_t)row * T);

    float sx = 0.f, sy = 0.f, sxx = 0.f, syy = 0.f, sxy = 0.f;

    // T/4 = 16384 float4 per row, 512 threads -> 32 iters/thread
    #pragma unroll 4
    for (int i = tid; i < T / 4; i += THREADS) {
        float4 x = __ldcs(&px[i]);
        float4 y = __ldcs(&py[i]);
        sx  += x.x + x.y + x.z + x.w;
        sy  += y.x + y.y + y.z + y.w;
        sxx += x.x * x.x + x.y * x.y + x.z * x.z + x.w * x.w;
        syy += y.x * y.x + y.y * y.y + y.z * y.z + y.w * y.w;
        sxy += x.x * y.x + x.y * y.y + x.z * y.z + x.w * y.w;
    }

    sx  = warp_sum(sx);
    sy  = warp_sum(sy);
    sxx = warp_sum(sxx);
    syy = warp_sum(syy);
    sxy = warp_sum(sxy);

    __shared__ float s[5][THREADS / 32];
    if (lane == 0) {
        s[0][wid] = sx;  s[1][wid] = sy;  s[2][wid] = sxx;
        s[3][wid] = syy; s[4][wid] = sxy;
    }
    __syncthreads();

    if (wid == 0) {
        const unsigned nW = THREADS / 32;  // 16
        float v0 = (lane < nW) ? s[0][lane] : 0.f;
        float v1 = (lane < nW) ? s[1][lane] : 0.f;
        float v2 = (lane < nW) ? s[2][lane] : 0.f;
        float v3 = (lane < nW) ? s[3][lane] : 0.f;
        float v4 = (lane < nW) ? s[4][lane] : 0.f;
        v0 = warp_sum(v0); v1 = warp_sum(v1); v2 = warp_sum(v2);
        v3 = warp_sum(v3); v4 = warp_sum(v4);
        if (lane == 0) {
            g_partials[row * 5 + 0] = v0;
            g_partials[row * 5 + 1] = v1;
            g_partials[row * 5 + 2] = v2;
            g_partials[row * 5 + 3] = v3;
            g_partials[row * 5 + 4] = v4;
        }
    }

    // ---- last-block finalize ----
    __shared__ bool isLast;
    if (tid == 0) {
        __threadfence();
        unsigned c = atomicAdd(&g_count, 1u);
        isLast = (c == (unsigned)gridDim.x - 1u);
    }
    __syncthreads();

    if (isLast) {
        const float invT = 1.0f / (float)T;
        // one thread per row (tid = 0..511)
        float fsx  = g_partials[tid * 5 + 0];
        float fsy  = g_partials[tid * 5 + 1];
        float fsxx = g_partials[tid * 5 + 2];
        float fsyy = g_partials[tid * 5 + 3];
        float fsxy = g_partials[tid * 5 + 4];

        float mx = fsx * invT;
        float my = fsy * invT;
        float var_x = fsxx * invT - mx * mx;
        float var_y = fsyy * invT - my * my;
        float cov   = fsxy * invT - mx * my;
        float dm = mx - my;
        float loss = 1.0f - 2.0f * cov / (var_x + var_y + dm * dm + EPS);

        loss = warp_sum(loss);
        __shared__ float sf[THREADS / 32];
        if (lane == 0) sf[wid] = loss;
        __syncthreads();
        if (wid == 0) {
            float v = (lane < THREADS / 32) ? sf[lane] : 0.f;
            v = warp_sum(v);
            if (lane == 0) {
                out[0] = v / (float)B;
                g_count = 0;  // reset for next graph replay
            }
        }
    }
}

extern "C" void kernel_launch(void* const* d_in, const int* in_sizes, int n_in,
                              void* d_out, int out_size) {
    const float* preds  = (const float*)d_in[0];
    const float* labels = (const float*)d_in[1];
    float* out = (float*)d_out;

    ccc_fused<<<B, THREADS>>>(preds, labels, out);
}

// round 5
// speedup vs baseline: 1.0795x; 1.0795x over previous
#include <cuda_runtime.h>

// CCC loss: B=512 rows, T=65536 cols, fp32.
// One CTA per row (512 x 512), unroll 4, plain float4 loads (R1 loop shape,
// the fastest measured), fused last-block finalize (threadfence-reduction).

#define B 512
#define T 65536
#define THREADS 512
#define EPS 1e-8f

__device__ float g_partials[B * 5];
__device__ unsigned int g_count;  // zero-init; reset by last block

__device__ __forceinline__ float warp_sum(float v) {
    #pragma unroll
    for (int o = 16; o > 0; o >>= 1)
        v += __shfl_down_sync(0xFFFFFFFFu, v, o);
    return v;
}

__global__ __launch_bounds__(THREADS)
void ccc_fused(const float* __restrict__ preds,
               const float* __restrict__ labels,
               float* __restrict__ out) {
    const int row  = blockIdx.x;
    const int tid  = threadIdx.x;
    const int lane = tid & 31;
    const int wid  = tid >> 5;

    const float4* px = reinterpret_cast<const float4*>(preds  + (size_t)row * T);
    const float4* py = reinterpret_cast<const float4*>(labels + (size_t)row * T);

    float sx = 0.f, sy = 0.f, sxx = 0.f, syy = 0.f, sxy = 0.f;

    // T/4 = 16384 float4 per row, 512 threads -> 32 iters/thread
    #pragma unroll 4
    for (int i = tid; i < T / 4; i += THREADS) {
        float4 x = px[i];
        float4 y = py[i];
        sx  += x.x + x.y + x.z + x.w;
        sy  += y.x + y.y + y.z + y.w;
        sxx += x.x * x.x + x.y * x.y + x.z * x.z + x.w * x.w;
        syy += y.x * y.x + y.y * y.y + y.z * y.z + y.w * y.w;
        sxy += x.x * y.x + x.y * y.y + x.z * y.z + x.w * y.w;
    }

    sx  = warp_sum(sx);
    sy  = warp_sum(sy);
    sxx = warp_sum(sxx);
    syy = warp_sum(syy);
    sxy = warp_sum(sxy);

    __shared__ float s[5][THREADS / 32];
    if (lane == 0) {
        s[0][wid] = sx;  s[1][wid] = sy;  s[2][wid] = sxx;
        s[3][wid] = syy; s[4][wid] = sxy;
    }
    __syncthreads();

    if (wid == 0) {
        const unsigned nW = THREADS / 32;  // 16
        float v0 = (lane < nW) ? s[0][lane] : 0.f;
        float v1 = (lane < nW) ? s[1][lane] : 0.f;
        float v2 = (lane < nW) ? s[2][lane] : 0.f;
        float v3 = (lane < nW) ? s[3][lane] : 0.f;
        float v4 = (lane < nW) ? s[4][lane] : 0.f;
        v0 = warp_sum(v0); v1 = warp_sum(v1); v2 = warp_sum(v2);
        v3 = warp_sum(v3); v4 = warp_sum(v4);
        if (lane == 0) {
            g_partials[row * 5 + 0] = v0;
            g_partials[row * 5 + 1] = v1;
            g_partials[row * 5 + 2] = v2;
            g_partials[row * 5 + 3] = v3;
            g_partials[row * 5 + 4] = v4;
        }
    }

    // ---- last-block finalize ----
    __shared__ bool isLast;
    if (tid == 0) {
        __threadfence();
        unsigned c = atomicAdd(&g_count, 1u);
        isLast = (c == (unsigned)gridDim.x - 1u);
    }
    __syncthreads();

    if (isLast) {
        const float invT = 1.0f / (float)T;
        // one thread per row (tid = 0..511)
        float fsx  = g_partials[tid * 5 + 0];
        float fsy  = g_partials[tid * 5 + 1];
        float fsxx = g_partials[tid * 5 + 2];
        float fsyy = g_partials[tid * 5 + 3];
        float fsxy = g_partials[tid * 5 + 4];

        float mx = fsx * invT;
        float my = fsy * invT;
        float var_x = fsxx * invT - mx * mx;
        float var_y = fsyy * invT - my * my;
        float cov   = fsxy * invT - mx * my;
        float dm = mx - my;
        float loss = 1.0f - 2.0f * cov / (var_x + var_y + dm * dm + EPS);

        loss = warp_sum(loss);
        __shared__ float sf[THREADS / 32];
        if (lane == 0) sf[wid] = loss;
        __syncthreads();
        if (wid == 0) {
            float v = (lane < THREADS / 32) ? sf[lane] : 0.f;
            v = warp_sum(v);
            if (lane == 0) {
                out[0] = v / (float)B;
                g_count = 0;  // reset for next graph replay
            }
        }
    }
}

extern "C" void kernel_launch(void* const* d_in, const int* in_sizes, int n_in,
                              void* d_out, int out_size) {
    const float* preds  = (const float*)d_in[0];
    const float* labels = (const float*)d_in[1];
    float* out = (float*)d_out;

    ccc_fused<<<B, THREADS>>>(preds, labels, out);
}

// round 6
// speedup vs baseline: 1.1006x; 1.0196x over previous
#include <cuda_runtime.h>

// CCC loss: B=512 rows, T=65536 cols, fp32.
// Best measured config (R2): one CTA per row (512 x 512), unroll 8,
// plain float4 loads, fused last-block finalize. Dead term removed.

#define B 512
#define T 65536
#define THREADS 512
#define EPS 1e-8f

__device__ float g_partials[B * 5];
__device__ unsigned int g_count;  // zero-init; reset by last block

__device__ __forceinline__ float warp_sum(float v) {
    #pragma unroll
    for (int o = 16; o > 0; o >>= 1)
        v += __shfl_down_sync(0xFFFFFFFFu, v, o);
    return v;
}

__global__ __launch_bounds__(THREADS)
void ccc_fused(const float* __restrict__ preds,
               const float* __restrict__ labels,
               float* __restrict__ out) {
    const int row  = blockIdx.x;
    const int tid  = threadIdx.x;
    const int lane = tid & 31;
    const int wid  = tid >> 5;

    const float4* px = reinterpret_cast<const float4*>(preds  + (size_t)row * T);
    const float4* py = reinterpret_cast<const float4*>(labels + (size_t)row * T);

    float sx = 0.f, sy = 0.f, sxx = 0.f, syy = 0.f, sxy = 0.f;

    // T/4 = 16384 float4 per row, 512 threads -> 32 iters/thread
    #pragma unroll 8
    for (int i = tid; i < T / 4; i += THREADS) {
        float4 x = px[i];
        float4 y = py[i];
        sx  += x.x + x.y + x.z + x.w;
        sy  += y.x + y.y + y.z + y.w;
        sxx += x.x * x.x + x.y * x.y + x.z * x.z + x.w * x.w;
        syy += y.x * y.x + y.y * y.y + y.z * y.z + y.w * y.w;
        sxy += x.x * y.x + x.y * y.y + x.z * y.z + x.w * y.w;
    }

    sx  = warp_sum(sx);
    sy  = warp_sum(sy);
    sxx = warp_sum(sxx);
    syy = warp_sum(syy);
    sxy = warp_sum(sxy);

    __shared__ float s[5][THREADS / 32];
    if (lane == 0) {
        s[0][wid] = sx;  s[1][wid] = sy;  s[2][wid] = sxx;
        s[3][wid] = syy; s[4][wid] = sxy;
    }
    __syncthreads();

    if (wid == 0) {
        const unsigned nW = THREADS / 32;  // 16
        float v0 = (lane < nW) ? s[0][lane] : 0.f;
        float v1 = (lane < nW) ? s[1][lane] : 0.f;
        float v2 = (lane < nW) ? s[2][lane] : 0.f;
        float v3 = (lane < nW) ? s[3][lane] : 0.f;
        float v4 = (lane < nW) ? s[4][lane] : 0.f;
        v0 = warp_sum(v0); v1 = warp_sum(v1); v2 = warp_sum(v2);
        v3 = warp_sum(v3); v4 = warp_sum(v4);
        if (lane == 0) {
            g_partials[row * 5 + 0] = v0;
            g_partials[row * 5 + 1] = v1;
            g_partials[row * 5 + 2] = v2;
            g_partials[row * 5 + 3] = v3;
            g_partials[row * 5 + 4] = v4;
        }
    }

    // ---- last-block finalize ----
    __shared__ bool isLast;
    if (tid == 0) {
        __threadfence();
        unsigned c = atomicAdd(&g_count, 1u);
        isLast = (c == (unsigned)gridDim.x - 1u);
    }
    __syncthreads();

    if (isLast) {
        const float invT = 1.0f / (float)T;
        // one thread per row (tid = 0..511)
        float fsx  = g_partials[tid * 5 + 0];
        float fsy  = g_partials[tid * 5 + 1];
        float fsxx = g_partials[tid * 5 + 2];
        float fsyy = g_partials[tid * 5 + 3];
        float fsxy = g_partials[tid * 5 + 4];

        float mx = fsx * invT;
        float my = fsy * invT;
        float var_x = fsxx * invT - mx * mx;
        float var_y = fsyy * invT - my * my;
        float cov   = fsxy * invT - mx * my;
        float dm = mx - my;
        float loss = 1.0f - 2.0f * cov / (var_x + var_y + dm * dm + EPS);

        loss = warp_sum(loss);
        __shared__ float sf[THREADS / 32];
        if (lane == 0) sf[wid] = loss;
        __syncthreads();
        if (wid == 0) {
            float v = (lane < THREADS / 32) ? sf[lane] : 0.f;
            v = warp_sum(v);
            if (lane == 0) {
                out[0] = v / (float)B;
                g_count = 0;  // reset for next graph replay
            }
        }
    }
}

extern "C" void kernel_launch(void* const* d_in, const int* in_sizes, int n_in,
                              void* d_out, int out_size) {
    const float* preds  = (const float*)d_in[0];
    const float* labels = (const float*)d_in[1];
    float* out = (float*)d_out;

    ccc_fused<<<B, THREADS>>>(preds, labels, out);
}

// round 7
// speedup vs baseline: 1.1588x; 1.0529x over previous
#include <cuda_runtime.h>

// CCC loss: B=512 rows, T=65536 cols, fp32.
// One CTA per row (512 x 512). Inner loop manually batches 4 independent
// LDG.128 (two iterations x two inputs) before consuming -> higher MLP
// within the 32-40 reg budget. Fused last-block finalize.

#define B 512
#define T 65536
#define THREADS 512
#define EPS 1e-8f

__device__ float g_partials[B * 5];
__device__ unsigned int g_count;  // zero-init; reset by last block

__device__ __forceinline__ float warp_sum(float v) {
    #pragma unroll
    for (int o = 16; o > 0; o >>= 1)
        v += __shfl_down_sync(0xFFFFFFFFu, v, o);
    return v;
}

__global__ __launch_bounds__(THREADS)
void ccc_fused(const float* __restrict__ preds,
               const float* __restrict__ labels,
               float* __restrict__ out) {
    const int row  = blockIdx.x;
    const int tid  = threadIdx.x;
    const int lane = tid & 31;
    const int wid  = tid >> 5;

    const float4* __restrict__ px =
        reinterpret_cast<const float4*>(preds  + (size_t)row * T);
    const float4* __restrict__ py =
        reinterpret_cast<const float4*>(labels + (size_t)row * T);

    float sx = 0.f, sy = 0.f, sxx = 0.f, syy = 0.f, sxy = 0.f;

    // 16384 float4 per row, 512 threads -> 32 iterations, processed 2 at a
    // time with all 4 loads issued before any consumption.
    #pragma unroll 2
    for (int j = 0; j < 32; j += 2) {
        const int iA = tid + j * THREADS;
        const int iB = iA + THREADS;
        float4 xa = px[iA];
        float4 ya = py[iA];
        float4 xb = px[iB];
        float4 yb = py[iB];

        sx  += xa.x + xa.y + xa.z + xa.w;
        sy  += ya.x + ya.y + ya.z + ya.w;
        sxx += xa.x * xa.x + xa.y * xa.y + xa.z * xa.z + xa.w * xa.w;
        syy += ya.x * ya.x + ya.y * ya.y + ya.z * ya.z + ya.w * ya.w;
        sxy += xa.x * ya.x + xa.y * ya.y + xa.z * ya.z + xa.w * ya.w;

        sx  += xb.x + xb.y + xb.z + xb.w;
        sy  += yb.x + yb.y + yb.z + yb.w;
        sxx += xb.x * xb.x + xb.y * xb.y + xb.z * xb.z + xb.w * xb.w;
        syy += yb.x * yb.x + yb.y * yb.y + yb.z * yb.z + yb.w * yb.w;
        sxy += xb.x * yb.x + xb.y * yb.y + xb.z * yb.z + xb.w * yb.w;
    }

    sx  = warp_sum(sx);
    sy  = warp_sum(sy);
    sxx = warp_sum(sxx);
    syy = warp_sum(syy);
    sxy = warp_sum(sxy);

    __shared__ float s[5][THREADS / 32];
    if (lane == 0) {
        s[0][wid] = sx;  s[1][wid] = sy;  s[2][wid] = sxx;
        s[3][wid] = syy; s[4][wid] = sxy;
    }
    __syncthreads();

    if (wid == 0) {
        const unsigned nW = THREADS / 32;  // 16
        float v0 = (lane < nW) ? s[0][lane] : 0.f;
        float v1 = (lane < nW) ? s[1][lane] : 0.f;
        float v2 = (lane < nW) ? s[2][lane] : 0.f;
        float v3 = (lane < nW) ? s[3][lane] : 0.f;
        float v4 = (lane < nW) ? s[4][lane] : 0.f;
        v0 = warp_sum(v0); v1 = warp_sum(v1); v2 = warp_sum(v2);
        v3 = warp_sum(v3); v4 = warp_sum(v4);
        if (lane == 0) {
            g_partials[row * 5 + 0] = v0;
            g_partials[row * 5 + 1] = v1;
            g_partials[row * 5 + 2] = v2;
            g_partials[row * 5 + 3] = v3;
            g_partials[row * 5 + 4] = v4;
        }
    }

    // ---- last-block finalize ----
    __shared__ bool isLast;
    if (tid == 0) {
        __threadfence();
        unsigned c = atomicAdd(&g_count, 1u);
        isLast = (c == (unsigned)gridDim.x - 1u);
    }
    __syncthreads();

    if (isLast) {
        const float invT = 1.0f / (float)T;
        // one thread per row (tid = 0..511)
        float fsx  = g_partials[tid * 5 + 0];
        float fsy  = g_partials[tid * 5 + 1];
        float fsxx = g_partials[tid * 5 + 2];
        float fsyy = g_partials[tid * 5 + 3];
        float fsxy = g_partials[tid * 5 + 4];

        float mx = fsx * invT;
        float my = fsy * invT;
        float var_x = fsxx * invT - mx * mx;
        float var_y = fsyy * invT - my * my;
        float cov   = fsxy * invT - mx * my;
        float dm = mx - my;
        float loss = 1.0f - 2.0f * cov / (var_x + var_y + dm * dm + EPS);

        loss = warp_sum(loss);
        __shared__ float sf[THREADS / 32];
        if (lane == 0) sf[wid] = loss;
        __syncthreads();
        if (wid == 0) {
            float v = (lane < THREADS / 32) ? sf[lane] : 0.f;
            v = warp_sum(v);
            if (lane == 0) {
                out[0] = v / (float)B;
                g_count = 0;  // reset for next graph replay
            }
        }
    }
}

extern "C" void kernel_launch(void* const* d_in, const int* in_sizes, int n_in,
                              void* d_out, int out_size) {
    const float* preds  = (const float*)d_in[0];
    const float* labels = (const float*)d_in[1];
    float* out = (float*)d_out;

    ccc_fused<<<B, THREADS>>>(preds, labels, out);
}